// round 1
// baseline (speedup 1.0000x reference)
#include <cuda_runtime.h>
#include <math.h>

#define BATCH    65536
#define D1       196
#define D2       206
#define NP       208        // padded dim (multiple of 16)
#define NSTR     212        // smem row stride for q/p/sq (mult of 4, kills bank conflicts)
#define KC       16         // K-chunk (13 chunks * 16 = 208)
#define NCH      13
#define TM       64         // batch rows per CTA
#define NTHREADS 256
#define DT       0.1f       // 0.5 / 5

__device__ float g_M1[NP * NP];
__device__ float g_M2[NP * NP];

// Build M = c2q(C) + Qn - I, zero-padded to NP x NP (row-major; M is symmetric).
__global__ void prep_kernel(const float* __restrict__ C,
                            const float* __restrict__ Qn,
                            int n, int which)
{
    float* M = which ? g_M2 : g_M1;
    const int j = blockIdx.x;
    __shared__ float red[NTHREADS];
    float s = 0.f;
    if (j < n) {
        for (int i = threadIdx.x; i < n; i += NTHREADS)
            s += 0.5f * (C[i * n + j] + C[j * n + i]);
    }
    red[threadIdx.x] = s;
    __syncthreads();
    for (int off = NTHREADS / 2; off > 0; off >>= 1) {
        if (threadIdx.x < off) red[threadIdx.x] += red[threadIdx.x + off];
        __syncthreads();
    }
    const float colsum = red[0];
    for (int i = threadIdx.x; i < NP; i += NTHREADS) {
        float v = 0.f;
        if (j < n && i < n) {
            if (i == j) v = -colsum + Qn[j * n + j] - 1.0f;
            else        v = 0.5f * (C[i * n + j] + C[j * n + i]) + Qn[i * n + j];
        }
        M[i * NP + j] = v;
    }
}

__global__ void __launch_bounds__(NTHREADS, 1)
net_kernel(const float* __restrict__ x,
           const float* __restrict__ b1,
           const float* __restrict__ b2,
           const float* __restrict__ facp,
           float* __restrict__ out)
{
    extern __shared__ float sm[];
    float* sqs = sm;                       // TM * NSTR
    float* qs  = sqs + TM * NSTR;          // TM * NSTR
    float* ps  = qs  + TM * NSTR;          // TM * NSTR
    float* Mb  = ps  + TM * NSTR;          // 2 * NP * KC (double-buffered M chunks)
    float* es  = Mb  + 2 * NP * KC;        // NP (bias, padded 0)

    const int tid  = threadIdx.x;
    const int tx   = tid & 15;             // column group (16)
    const int ty   = tid >> 4;             // row group (16)
    const int row0 = ty * 4;
    const int rowg = blockIdx.x * TM;

    // ---- init stage-1 state: q = x (zero-padded), bias e1 ----
    #pragma unroll
    for (int c = 0; c < 13; c++) {
        const int col = tx + 16 * c;
        #pragma unroll
        for (int r = 0; r < 4; r++) {
            float v = 0.f;
            if (col < D1) v = x[(rowg + row0 + r) * D1 + col];
            qs[(row0 + r) * NSTR + col] = v;
        }
    }
    for (int i = tid; i < NP; i += NTHREADS) es[i] = (i < D1) ? b1[i] : 0.f;
    __syncthreads();

    // sq = sin(1.1 * q) for this thread's own cells (pads stay exactly 0)
    auto calc_sq = [&] {
        #pragma unroll
        for (int c = 0; c < 13; c++) {
            const int col = tx + 16 * c;
            #pragma unroll
            for (int r = 0; r < 4; r++) {
                const int i = (row0 + r) * NSTR + col;
                sqs[i] = sinf(1.1f * qs[i]);
            }
        }
    };

    float acc[4][13];

    // acc[r][c] = e[col] + sum_k sq[row][k] * M[k][col]   (M symmetric -> read rows)
    auto gemm = [&](const float* __restrict__ Mg) {
        #pragma unroll
        for (int c = 0; c < 13; c++) {
            const float ec = es[tx + 16 * c];
            #pragma unroll
            for (int r = 0; r < 4; r++) acc[r][c] = ec;
        }
        // preload chunk 0 : Mb[j][0..15] = M[j][0..15]
        {
            float4* dst = (float4*)Mb;
            const float4* src = (const float4*)Mg;
            for (int idx = tid; idx < NP * (KC / 4); idx += NTHREADS) {
                const int j = idx >> 2, v = idx & 3;
                dst[j * (KC / 4) + v] = src[j * (NP / 4) + v];
            }
        }
        __syncthreads();
        for (int ch = 0; ch < NCH; ch++) {
            const float* cur = Mb + (ch & 1) * NP * KC;
            if (ch + 1 < NCH) {
                float4* dst = (float4*)(Mb + ((ch + 1) & 1) * NP * KC);
                const float4* src = (const float4*)(Mg + (ch + 1) * KC);
                for (int idx = tid; idx < NP * (KC / 4); idx += NTHREADS) {
                    const int j = idx >> 2, v = idx & 3;
                    dst[j * (KC / 4) + v] = src[j * (NP / 4) + v];
                }
            }
            const int k0 = ch * KC;
            #pragma unroll
            for (int k4 = 0; k4 < KC / 4; k4++) {
                float4 sv[4];
                #pragma unroll
                for (int r = 0; r < 4; r++)
                    sv[r] = *(const float4*)&sqs[(row0 + r) * NSTR + k0 + 4 * k4];
                #pragma unroll
                for (int c = 0; c < 13; c++) {
                    const float4 mv =
                        *(const float4*)&cur[(tx + 16 * c) * KC + 4 * k4];
                    #pragma unroll
                    for (int r = 0; r < 4; r++) {
                        acc[r][c] = fmaf(sv[r].x, mv.x, acc[r][c]);
                        acc[r][c] = fmaf(sv[r].y, mv.y, acc[r][c]);
                        acc[r][c] = fmaf(sv[r].z, mv.z, acc[r][c]);
                        acc[r][c] = fmaf(sv[r].w, mv.w, acc[r][c]);
                    }
                }
            }
            __syncthreads();
        }
    };

    // ================= STAGE 1 (3 full evals) =================
    // E0 = g(q0): q <- q0 + dt^2*E0 (=q2), p <- 2dt*E0 (=p2)
    calc_sq(); __syncthreads();
    gemm(g_M1);
    #pragma unroll
    for (int c = 0; c < 13; c++) {
        const int col = tx + 16 * c;
        #pragma unroll
        for (int r = 0; r < 4; r++) {
            const int i = (row0 + r) * NSTR + col;
            const float a = acc[r][c];
            qs[i] += DT * DT * a;
            ps[i]  = 2.f * DT * a;
        }
    }
    __syncthreads();
    // E2 = g(q2): q <- q + dt*p (=q3), p <- p + dt*E2 (=p3)
    calc_sq(); __syncthreads();
    gemm(g_M1);
    #pragma unroll
    for (int c = 0; c < 13; c++) {
        const int col = tx + 16 * c;
        #pragma unroll
        for (int r = 0; r < 4; r++) {
            const int i = (row0 + r) * NSTR + col;
            const float po = ps[i];
            qs[i] += DT * po;
            ps[i]  = po + DT * acc[r][c];
        }
    }
    __syncthreads();
    // E3 = g(q3): q5 = q + 2dt*p + dt^2*E3   (p discarded)
    calc_sq(); __syncthreads();
    gemm(g_M1);
    #pragma unroll
    for (int c = 0; c < 13; c++) {
        const int col = tx + 16 * c;
        #pragma unroll
        for (int r = 0; r < 4; r++) {
            const int i = (row0 + r) * NSTR + col;
            qs[i] += 2.f * DT * ps[i] + DT * DT * acc[r][c];
        }
    }
    __syncthreads();

    // ================= STAGE 2 (1 full + 2 skinny evals) =================
    // q cols [196,208) are already exactly 0; p fully overwritten below.
    for (int i = tid; i < NP; i += NTHREADS) es[i] = (i < D2) ? b2[i] : 0.f;
    __syncthreads();
    // E0 full
    calc_sq(); __syncthreads();
    gemm(g_M2);
    #pragma unroll
    for (int c = 0; c < 13; c++) {
        const int col = tx + 16 * c;
        #pragma unroll
        for (int r = 0; r < 4; r++) {
            const int i = (row0 + r) * NSTR + col;
            const float a = acc[r][c];
            qs[i] += DT * DT * a;
            ps[i]  = 2.f * DT * a;
        }
    }
    // tail of M2 (columns 196..205) into Mb for the skinny matmuls
    for (int idx = tid; idx < D2 * 10; idx += NTHREADS) {
        const int k = idx / 10, jj = idx - k * 10;
        Mb[k * 12 + jj] = g_M2[k * NP + 196 + jj];
    }
    __syncthreads();

    const int srow = tid >> 2;            // skinny mapping: 64 rows x 4 groups
    const int g    = tid & 3;

    // E2 skinny (last-10 cols only)
    calc_sq(); __syncthreads();
    float a2[3];
    {
        #pragma unroll
        for (int m = 0; m < 3; m++) a2[m] = es[196 + g + 4 * m];
        const float* sr = &sqs[srow * NSTR];
        #pragma unroll 2
        for (int k = 0; k < D2; k++) {
            const float s = sr[k];
            #pragma unroll
            for (int m = 0; m < 3; m++) a2[m] += s * Mb[k * 12 + g + 4 * m];
        }
    }
    // q <- q + dt*p (full, uses old p)
    #pragma unroll
    for (int c = 0; c < 13; c++) {
        const int col = tx + 16 * c;
        #pragma unroll
        for (int r = 0; r < 4; r++) {
            const int i = (row0 + r) * NSTR + col;
            qs[i] += DT * ps[i];
        }
    }
    __syncthreads();
    // p[last10] <- p + dt*E2
    #pragma unroll
    for (int m = 0; m < 3; m++) {
        const int j = 196 + g + 4 * m;
        if (j < D2) ps[srow * NSTR + j] += DT * a2[m];
    }
    __syncthreads();

    // E3 skinny at q3, then output q5 = q3 + 2dt*p3 + dt^2*E3
    calc_sq(); __syncthreads();
    float a3[3];
    {
        #pragma unroll
        for (int m = 0; m < 3; m++) a3[m] = es[196 + g + 4 * m];
        const float* sr = &sqs[srow * NSTR];
        #pragma unroll 2
        for (int k = 0; k < D2; k++) {
            const float s = sr[k];
            #pragma unroll
            for (int m = 0; m < 3; m++) a3[m] += s * Mb[k * 12 + g + 4 * m];
        }
    }
    const float fac = *facp;
    #pragma unroll
    for (int m = 0; m < 3; m++) {
        const int j = 196 + g + 4 * m;
        if (j < D2) {
            const float q5 = qs[srow * NSTR + j]
                           + 2.f * DT * ps[srow * NSTR + j]
                           + DT * DT * a3[m];
            out[(rowg + srow) * 10 + (j - 196)] = fac * q5;
        }
    }
}

extern "C" void kernel_launch(void* const* d_in, const int* in_sizes, int n_in,
                              void* d_out, int out_size)
{
    const float* x    = (const float*)d_in[0];
    const float* fc1w = (const float*)d_in[1];
    const float* fc1b = (const float*)d_in[2];
    const float* fc2w = (const float*)d_in[3];
    const float* fc2b = (const float*)d_in[4];
    const float* fac  = (const float*)d_in[5];
    const float* qn1  = (const float*)d_in[6];
    const float* qn2  = (const float*)d_in[7];
    float* out = (float*)d_out;

    prep_kernel<<<NP, NTHREADS>>>(fc1w, qn1, D1, 0);
    prep_kernel<<<NP, NTHREADS>>>(fc2w, qn2, D2, 1);

    const int smem = (3 * TM * NSTR + 2 * NP * KC + NP) * (int)sizeof(float);
    cudaFuncSetAttribute(net_kernel,
                         cudaFuncAttributeMaxDynamicSharedMemorySize, smem);
    net_kernel<<<BATCH / TM, NTHREADS, smem>>>(x, fc1b, fc2b, fac, out);
}

// round 2
// speedup vs baseline: 2.3724x; 2.3724x over previous
#include <cuda_runtime.h>
#include <math.h>

#define BATCH    65536
#define D1       196
#define D2       206
#define NP       208        // padded dim (multiple of 16)
#define NSTR     212        // smem row stride for q/p/sq
#define KC       16         // K-chunk (13 chunks * 16 = 208)
#define KSTR     20         // padded column stride inside Mb (80B: conflict-free LDS.128)
#define NCH      13
#define TM       64         // batch rows per CTA
#define NTHREADS 256
#define DT       0.1f       // 0.5 / 5

__device__ float g_M1[NP * NP];
__device__ float g_M2[NP * NP];

typedef unsigned long long u64;

// pack two floats into a 64-bit f32x2 carrier
__device__ __forceinline__ u64 pk2(float lo, float hi) {
    u64 r;
    asm("mov.b64 %0, {%1,%2};" : "=l"(r) : "f"(lo), "f"(hi));
    return r;
}
// packed fma: d = a*b + d (elementwise f32x2)  [sm_10x FFMA2]
__device__ __forceinline__ void ffma2(u64& d, u64 a, u64 b) {
    asm("fma.rn.f32x2 %0, %1, %2, %0;" : "+l"(d) : "l"(a), "l"(b));
}
// horizontal fold of a packed pair
__device__ __forceinline__ float unpk_sum(u64 v) {
    float lo, hi;
    asm("mov.b64 {%0,%1}, %2;" : "=f"(lo), "=f"(hi) : "l"(v));
    return lo + hi;
}

// Build M = c2q(C) + Qn - I, zero-padded to NP x NP (row-major; M is symmetric).
__global__ void prep_kernel(const float* __restrict__ C,
                            const float* __restrict__ Qn,
                            int n, int which)
{
    float* M = which ? g_M2 : g_M1;
    const int j = blockIdx.x;
    __shared__ float red[NTHREADS];
    float s = 0.f;
    if (j < n) {
        for (int i = threadIdx.x; i < n; i += NTHREADS)
            s += 0.5f * (C[i * n + j] + C[j * n + i]);
    }
    red[threadIdx.x] = s;
    __syncthreads();
    for (int off = NTHREADS / 2; off > 0; off >>= 1) {
        if (threadIdx.x < off) red[threadIdx.x] += red[threadIdx.x + off];
        __syncthreads();
    }
    const float colsum = red[0];
    for (int i = threadIdx.x; i < NP; i += NTHREADS) {
        float v = 0.f;
        if (j < n && i < n) {
            if (i == j) v = -colsum + Qn[j * n + j] - 1.0f;
            else        v = 0.5f * (C[i * n + j] + C[j * n + i]) + Qn[i * n + j];
        }
        M[i * NP + j] = v;
    }
}

__global__ void __launch_bounds__(NTHREADS, 1)
net_kernel(const float* __restrict__ x,
           const float* __restrict__ b1,
           const float* __restrict__ b2,
           const float* __restrict__ facp,
           float* __restrict__ out)
{
    extern __shared__ float sm[];
    float* sqs = sm;                       // TM * NSTR
    float* qs  = sqs + TM * NSTR;          // TM * NSTR
    float* ps  = qs  + TM * NSTR;          // TM * NSTR
    float* Mb  = ps  + TM * NSTR;          // 2 * NP * KSTR (double-buffered M chunks)
    float* es  = Mb  + 2 * NP * KSTR;      // NP (bias, padded 0)

    const int tid  = threadIdx.x;
    const int tx   = tid & 15;             // column group (16)
    const int ty   = tid >> 4;             // row group (16)
    const int row0 = ty * 4;
    const int rowg = blockIdx.x * TM;

    // ---- init stage-1 state: q = x (zero-padded), bias e1 ----
    #pragma unroll
    for (int c = 0; c < 13; c++) {
        const int col = tx + 16 * c;
        #pragma unroll
        for (int r = 0; r < 4; r++) {
            float v = 0.f;
            if (col < D1) v = x[(rowg + row0 + r) * D1 + col];
            qs[(row0 + r) * NSTR + col] = v;
        }
    }
    for (int i = tid; i < NP; i += NTHREADS) es[i] = (i < D1) ? b1[i] : 0.f;
    __syncthreads();

    // sq = sin(1.1 * q) for this thread's own cells (pads stay exactly 0)
    auto calc_sq = [&] {
        #pragma unroll
        for (int c = 0; c < 13; c++) {
            const int col = tx + 16 * c;
            #pragma unroll
            for (int r = 0; r < 4; r++) {
                const int i = (row0 + r) * NSTR + col;
                sqs[i] = __sinf(1.1f * qs[i]);
            }
        }
    };

    u64 acc2[4][13];   // packed even/odd-k partial sums

    // acc[r][c] = sum_k sq[row][k] * M[k][col]   (M symmetric -> read rows)
    auto gemm = [&](const float* __restrict__ Mg) {
        #pragma unroll
        for (int c = 0; c < 13; c++)
            #pragma unroll
            for (int r = 0; r < 4; r++) acc2[r][c] = 0ull;
        // preload chunk 0 into buffer 0 (padded column stride KSTR)
        {
            float4* dst = (float4*)Mb;
            const float4* src = (const float4*)Mg;
            for (int idx = tid; idx < NP * 4; idx += NTHREADS) {
                const int j = idx >> 2, v = idx & 3;
                dst[j * (KSTR / 4) + v] = src[j * (NP / 4) + v];
            }
        }
        __syncthreads();
        for (int ch = 0; ch < NCH; ch++) {
            const float* cur = Mb + (ch & 1) * NP * KSTR;
            if (ch + 1 < NCH) {
                float4* dst = (float4*)(Mb + ((ch + 1) & 1) * NP * KSTR);
                const float4* src = (const float4*)Mg;
                const int co = (ch + 1) * (KC / 4);
                for (int idx = tid; idx < NP * 4; idx += NTHREADS) {
                    const int j = idx >> 2, v = idx & 3;
                    dst[j * (KSTR / 4) + v] = src[j * (NP / 4) + co + v];
                }
            }
            const int k0 = ch * KC;
            #pragma unroll
            for (int k4 = 0; k4 < KC / 4; k4++) {
                u64 sp[4][2];
                #pragma unroll
                for (int r = 0; r < 4; r++) {
                    const float4 sv =
                        *(const float4*)&sqs[(row0 + r) * NSTR + k0 + 4 * k4];
                    sp[r][0] = pk2(sv.x, sv.y);
                    sp[r][1] = pk2(sv.z, sv.w);
                }
                #pragma unroll
                for (int c = 0; c < 13; c++) {
                    const float4 mv =
                        *(const float4*)&cur[(tx + 16 * c) * KSTR + 4 * k4];
                    const u64 mp0 = pk2(mv.x, mv.y);
                    const u64 mp1 = pk2(mv.z, mv.w);
                    #pragma unroll
                    for (int r = 0; r < 4; r++) {
                        ffma2(acc2[r][c], sp[r][0], mp0);
                        ffma2(acc2[r][c], sp[r][1], mp1);
                    }
                }
            }
            __syncthreads();
        }
    };

    // ================= STAGE 1 (3 full evals) =================
    // E0 = g(q0): q <- q0 + dt^2*E0 (=q2), p <- 2dt*E0 (=p2)
    calc_sq(); __syncthreads();
    gemm(g_M1);
    #pragma unroll
    for (int c = 0; c < 13; c++) {
        const int col = tx + 16 * c;
        const float ec = es[col];
        #pragma unroll
        for (int r = 0; r < 4; r++) {
            const int i = (row0 + r) * NSTR + col;
            const float a = ec + unpk_sum(acc2[r][c]);
            qs[i] += DT * DT * a;
            ps[i]  = 2.f * DT * a;
        }
    }
    __syncthreads();
    // E2 = g(q2): q <- q + dt*p (=q3), p <- p + dt*E2 (=p3)
    calc_sq(); __syncthreads();
    gemm(g_M1);
    #pragma unroll
    for (int c = 0; c < 13; c++) {
        const int col = tx + 16 * c;
        const float ec = es[col];
        #pragma unroll
        for (int r = 0; r < 4; r++) {
            const int i = (row0 + r) * NSTR + col;
            const float po = ps[i];
            qs[i] += DT * po;
            ps[i]  = po + DT * (ec + unpk_sum(acc2[r][c]));
        }
    }
    __syncthreads();
    // E3 = g(q3): q5 = q + 2dt*p + dt^2*E3   (p discarded)
    calc_sq(); __syncthreads();
    gemm(g_M1);
    #pragma unroll
    for (int c = 0; c < 13; c++) {
        const int col = tx + 16 * c;
        const float ec = es[col];
        #pragma unroll
        for (int r = 0; r < 4; r++) {
            const int i = (row0 + r) * NSTR + col;
            qs[i] += 2.f * DT * ps[i] + DT * DT * (ec + unpk_sum(acc2[r][c]));
        }
    }
    __syncthreads();

    // ================= STAGE 2 (1 full + 2 skinny evals) =================
    // q cols [196,208) are already exactly 0; p fully overwritten below.
    for (int i = tid; i < NP; i += NTHREADS) es[i] = (i < D2) ? b2[i] : 0.f;
    __syncthreads();
    // E0 full
    calc_sq(); __syncthreads();
    gemm(g_M2);
    #pragma unroll
    for (int c = 0; c < 13; c++) {
        const int col = tx + 16 * c;
        const float ec = es[col];
        #pragma unroll
        for (int r = 0; r < 4; r++) {
            const int i = (row0 + r) * NSTR + col;
            const float a = ec + unpk_sum(acc2[r][c]);
            qs[i] += DT * DT * a;
            ps[i]  = 2.f * DT * a;
        }
    }
    // tail of M2 (columns 196..205) into Mb for the skinny matmuls
    for (int idx = tid; idx < D2 * 10; idx += NTHREADS) {
        const int k = idx / 10, jj = idx - k * 10;
        Mb[k * 12 + jj] = g_M2[k * NP + 196 + jj];
    }
    __syncthreads();

    const int srow = tid >> 2;            // skinny mapping: 64 rows x 4 groups
    const int g    = tid & 3;

    // E2 skinny (last-10 cols only)
    calc_sq(); __syncthreads();
    float a2[3];
    {
        #pragma unroll
        for (int m = 0; m < 3; m++) a2[m] = es[196 + g + 4 * m];
        const float* sr = &sqs[srow * NSTR];
        #pragma unroll 2
        for (int k = 0; k < D2; k++) {
            const float s = sr[k];
            #pragma unroll
            for (int m = 0; m < 3; m++) a2[m] += s * Mb[k * 12 + g + 4 * m];
        }
    }
    // q <- q + dt*p (full, uses old p)
    #pragma unroll
    for (int c = 0; c < 13; c++) {
        const int col = tx + 16 * c;
        #pragma unroll
        for (int r = 0; r < 4; r++) {
            const int i = (row0 + r) * NSTR + col;
            qs[i] += DT * ps[i];
        }
    }
    __syncthreads();
    // p[last10] <- p + dt*E2
    #pragma unroll
    for (int m = 0; m < 3; m++) {
        const int j = 196 + g + 4 * m;
        if (j < D2) ps[srow * NSTR + j] += DT * a2[m];
    }
    __syncthreads();

    // E3 skinny at q3, then output q5 = q3 + 2dt*p3 + dt^2*E3
    calc_sq(); __syncthreads();
    float a3[3];
    {
        #pragma unroll
        for (int m = 0; m < 3; m++) a3[m] = es[196 + g + 4 * m];
        const float* sr = &sqs[srow * NSTR];
        #pragma unroll 2
        for (int k = 0; k < D2; k++) {
            const float s = sr[k];
            #pragma unroll
            for (int m = 0; m < 3; m++) a3[m] += s * Mb[k * 12 + g + 4 * m];
        }
    }
    const float fac = *facp;
    #pragma unroll
    for (int m = 0; m < 3; m++) {
        const int j = 196 + g + 4 * m;
        if (j < D2) {
            const float q5 = qs[srow * NSTR + j]
                           + 2.f * DT * ps[srow * NSTR + j]
                           + DT * DT * a3[m];
            out[(rowg + srow) * 10 + (j - 196)] = fac * q5;
        }
    }
}

extern "C" void kernel_launch(void* const* d_in, const int* in_sizes, int n_in,
                              void* d_out, int out_size)
{
    const float* x    = (const float*)d_in[0];
    const float* fc1w = (const float*)d_in[1];
    const float* fc1b = (const float*)d_in[2];
    const float* fc2w = (const float*)d_in[3];
    const float* fc2b = (const float*)d_in[4];
    const float* fac  = (const float*)d_in[5];
    const float* qn1  = (const float*)d_in[6];
    const float* qn2  = (const float*)d_in[7];
    float* out = (float*)d_out;

    prep_kernel<<<NP, NTHREADS>>>(fc1w, qn1, D1, 0);
    prep_kernel<<<NP, NTHREADS>>>(fc2w, qn2, D2, 1);

    const int smem = (3 * TM * NSTR + 2 * NP * KSTR + NP) * (int)sizeof(float);
    cudaFuncSetAttribute(net_kernel,
                         cudaFuncAttributeMaxDynamicSharedMemorySize, smem);
    net_kernel<<<BATCH / TM, NTHREADS, smem>>>(x, fc1b, fc2b, fac, out);
}